// round 10
// baseline (speedup 1.0000x reference)
#include <cuda_runtime.h>
#include <cuda_bf16.h>
#include <cstdint>
#include <cstddef>

namespace {
constexpr int kB    = 128;
constexpr int kT    = 65536;
constexpr int kE    = 512;
constexpr int kSmax = 512;

constexpr int BM = 128;
constexpr int BN = 128;
constexpr int KC = 64;

constexpr int NTHREADS = 128;   // 4 warps: 2(m) x 2(n), warp tile 64x64

constexpr int LDSF = 68;        // smem row stride in floats (conflict-free scalar LDS)

constexpr int OFF_A = 0;                        // 128 x 68 floats
constexpr int OFF_B = BM * LDSF;                // 8704
constexpr int SMEM_FLOATS = OFF_B + BN * LDSF;  // 17408
constexpr int SMEM_BYTES  = SMEM_FLOATS * 4;    // 69632
}

__device__ int g_nvalid[kB];
__device__ int g_cnt[kB];
__device__ int g_done[kB];

// ---------------------------------------------------------------------------
__device__ __forceinline__ uint32_t f2tf32(float x) {
    uint32_t r;
    asm("cvt.rna.tf32.f32 %0, %1;" : "=r"(r) : "f"(x));
    return r;
}

__device__ __forceinline__ void mma_tf32(float* c, const uint32_t* a, const uint32_t* b) {
    asm volatile(
        "mma.sync.aligned.m16n8k8.row.col.f32.tf32.tf32.f32 "
        "{%0,%1,%2,%3}, {%4,%5,%6,%7}, {%8,%9}, {%0,%1,%2,%3};"
        : "+f"(c[0]), "+f"(c[1]), "+f"(c[2]), "+f"(c[3])
        : "r"(a[0]), "r"(a[1]), "r"(a[2]), "r"(a[3]), "r"(b[0]), "r"(b[1]));
}

// ---------------------------------------------------------------------------
// Kernel A: 8 blocks/sample popcount, atomic reduce; last block finalizes.
// ---------------------------------------------------------------------------
__global__ __launch_bounds__(256) void len_mask_kernel(
    const int* __restrict__ mask,
    const int* __restrict__ branch_idx,
    float* __restrict__ out,
    int write_mask)
{
    const int b = blockIdx.x >> 3;
    const int q = blockIdx.x & 7;
    const int t = threadIdx.x;

    const uint4* p = reinterpret_cast<const uint4*>(mask + (size_t)b * kT) + q * 2048;
    int sum = 0;
#pragma unroll 4
    for (int i = t; i < 2048; i += 256) {
        uint4 v = p[i];
        sum += (int)((v.x & 1u) + (v.y & 1u) + (v.z & 1u) + (v.w & 1u));
    }
#pragma unroll
    for (int o = 16; o > 0; o >>= 1) sum += __shfl_down_sync(0xffffffffu, sum, o);

    __shared__ int warp_sums[8];
    __shared__ int is_last;
    if ((t & 31) == 0) warp_sums[t >> 5] = sum;
    __syncthreads();
    if (t == 0) {
        int tot = 0;
#pragma unroll
        for (int i = 0; i < 8; i++) tot += warp_sums[i];
        atomicAdd(&g_cnt[b], tot);
        __threadfence();
        int old = atomicAdd(&g_done[b], 1);
        is_last = (old == 7);
    }
    __syncthreads();

    if (!is_last) return;

    __shared__ int nv_sh;
    if (t == 0) {
        __threadfence();
        int tot = atomicAdd(&g_cnt[b], 0);
        int bi = branch_idx[b];
        int w  = 128 << bi;
        int Sb = kT / w;
        int nv = tot / w;
        if (nv > Sb) nv = Sb;
        g_nvalid[b] = nv;
        nv_sh = nv;
        g_cnt[b]  = 0;
        g_done[b] = 0;
    }
    __syncthreads();

    if (write_mask) {
        int nv = nv_sh;
        float* mout = out + (size_t)kB * kSmax * kE + (size_t)b * kSmax;
        for (int s = t; s < kSmax; s += 256) mout[s] = (s < nv) ? 1.0f : 0.0f;
    }
}

// ---------------------------------------------------------------------------
// Kernel B: tf32 mma.sync GEMM, warp tile 64x64 (high smem reuse).
// 128 threads, tile 128x128, 2 CTAs/SM. Grid (4, 4, 128).
// ---------------------------------------------------------------------------
__global__ __launch_bounds__(NTHREADS, 2) void branch_gemm_mma(
    const float* __restrict__ signal,
    const int*   __restrict__ branch_idx,
    const float* __restrict__ W0, const float* __restrict__ b0,
    const float* __restrict__ W1, const float* __restrict__ b1,
    const float* __restrict__ W2, const float* __restrict__ b2,
    float* __restrict__ out)
{
    extern __shared__ float smemf[];
    const int tid  = threadIdx.x;
    const int b    = blockIdx.z;
    const int m0   = blockIdx.y * BM;
    const int n0   = blockIdx.x * BN;

    float* outb = out + (size_t)b * kSmax * kE;
    const int nv = g_nvalid[b];

    if (m0 >= nv) {
        float4 z = make_float4(0.f, 0.f, 0.f, 0.f);
#pragma unroll
        for (int i = 0; i < 32; i++) {
            int u   = tid + i * NTHREADS;     // 4096 float4 = 128x128 floats
            int row = u >> 5;
            int c4  = (u & 31) << 2;
            *reinterpret_cast<float4*>(outb + (size_t)(m0 + row) * kE + n0 + c4) = z;
        }
        return;
    }

    const int bi   = branch_idx[b];
    const int logw = 7 + bi;
    const int nchunks = (1 << logw) / KC;     // 2, 4, 8
    const float* Wp = (bi == 0) ? W0 : (bi == 1) ? W1 : W2;
    const float* bp = (bi == 0) ? b0 : (bi == 1) ? b1 : b2;
    const float* Asrc = signal + (size_t)b * kT + ((size_t)m0 << logw);
    const float* Bsrc = Wp + ((size_t)n0 << logw);

    const int lane   = tid & 31;
    const int warp   = tid >> 5;
    const int warp_m = warp & 1;        // m offset *64
    const int warp_n = warp >> 1;       // n offset *64
    const int g      = lane >> 2;       // 0..7
    const int tg     = lane & 3;

    const uint32_t aBase = OFF_A + (warp_m * 64 + g) * LDSF + tg;
    const uint32_t bBase = OFF_B + (warp_n * 64 + g) * LDSF + tg;

    float acc[4][8][4];
#pragma unroll
    for (int mi = 0; mi < 4; mi++)
#pragma unroll
        for (int nj = 0; nj < 8; nj++)
#pragma unroll
            for (int q = 0; q < 4; q++) acc[mi][nj][q] = 0.f;

    // loader: 16 threads/row (64 cols), 8 rows per pass, 16 passes for 128 rows
    const int srow = tid >> 4;
    const int sc4  = (tid & 15) << 2;

    for (int c = 0; c < nchunks; c++) {
        const int kk = c * KC;
        if (c) __syncthreads();

        // fill A (128 x 64)
#pragma unroll
        for (int i = 0; i < 16; i++) {
            int row = srow + i * 8;
            float4 v = *reinterpret_cast<const float4*>(Asrc + ((size_t)row << logw) + kk + sc4);
            uint4 t4 = make_uint4(f2tf32(v.x), f2tf32(v.y), f2tf32(v.z), f2tf32(v.w));
            *reinterpret_cast<uint4*>(smemf + OFF_A + row * LDSF + sc4) = t4;
        }
        // fill B (128 x 64)
#pragma unroll
        for (int i = 0; i < 16; i++) {
            int row = srow + i * 8;
            float4 v = *reinterpret_cast<const float4*>(Bsrc + ((size_t)row << logw) + kk + sc4);
            uint4 t4 = make_uint4(f2tf32(v.x), f2tf32(v.y), f2tf32(v.z), f2tf32(v.w));
            *reinterpret_cast<uint4*>(smemf + OFF_B + row * LDSF + sc4) = t4;
        }
        __syncthreads();

        // compute: 8 k8 steps, 32 MMAs each
        const uint32_t* sm = reinterpret_cast<const uint32_t*>(smemf);
#pragma unroll
        for (int s = 0; s < 8; s++) {
            const uint32_t ko = s * 8;
            uint32_t af[4][4], bf[8][2];
#pragma unroll
            for (int mi = 0; mi < 4; mi++) {
                uint32_t base = aBase + mi * 16 * LDSF + ko;
                af[mi][0] = sm[base];
                af[mi][1] = sm[base + 8 * LDSF];
                af[mi][2] = sm[base + 4];
                af[mi][3] = sm[base + 8 * LDSF + 4];
            }
#pragma unroll
            for (int nj = 0; nj < 8; nj++) {
                uint32_t base = bBase + nj * 8 * LDSF + ko;
                bf[nj][0] = sm[base];
                bf[nj][1] = sm[base + 4];
            }
#pragma unroll
            for (int mi = 0; mi < 4; mi++)
#pragma unroll
                for (int nj = 0; nj < 8; nj++)
                    mma_tf32(acc[mi][nj], af[mi], bf[nj]);
        }
    }

    // Epilogue
    const int col0 = tg * 2;
    const int rbase = m0 + warp_m * 64 + g;
    const int ncol  = n0 + warp_n * 64;
#pragma unroll
    for (int mi = 0; mi < 4; mi++) {
        int r0 = rbase + mi * 16;
        int r1 = r0 + 8;
        bool v0 = r0 < nv, v1 = r1 < nv;
        float* o0p = outb + (size_t)r0 * kE + ncol + col0;
        float* o1p = outb + (size_t)r1 * kE + ncol + col0;
#pragma unroll
        for (int nj = 0; nj < 8; nj++) {
            float2 bias = *reinterpret_cast<const float2*>(bp + ncol + nj * 8 + col0);
            float2 o0 = v0 ? make_float2(acc[mi][nj][0] + bias.x, acc[mi][nj][1] + bias.y)
                           : make_float2(0.f, 0.f);
            float2 o1 = v1 ? make_float2(acc[mi][nj][2] + bias.x, acc[mi][nj][3] + bias.y)
                           : make_float2(0.f, 0.f);
            *reinterpret_cast<float2*>(o0p + nj * 8) = o0;
            *reinterpret_cast<float2*>(o1p + nj * 8) = o1;
        }
    }
}

// ---------------------------------------------------------------------------
extern "C" void kernel_launch(void* const* d_in, const int* in_sizes, int n_in,
                              void* d_out, int out_size)
{
    const float* signal = (const float*)d_in[0];
    const int*   mask   = (const int*)d_in[1];
    const int*   bidx   = (const int*)d_in[2];
    const float* W0 = (const float*)d_in[3];
    const float* b0 = (const float*)d_in[4];
    const float* W1 = (const float*)d_in[5];
    const float* b1 = (const float*)d_in[6];
    const float* W2 = (const float*)d_in[7];
    const float* b2 = (const float*)d_in[8];
    float* out = (float*)d_out;

    int write_mask = (out_size > kB * kSmax * kE) ? 1 : 0;

    len_mask_kernel<<<kB * 8, 256>>>(mask, bidx, out, write_mask);

    static bool attr_set = false;
    if (!attr_set) {
        cudaFuncSetAttribute(branch_gemm_mma,
                             cudaFuncAttributeMaxDynamicSharedMemorySize, SMEM_BYTES);
        attr_set = true;
    }
    dim3 grid(kE / BN, kSmax / BM, kB);
    branch_gemm_mma<<<grid, NTHREADS, SMEM_BYTES>>>(signal, bidx, W0, b0, W1, b1, W2, b2, out);
}

// round 11
// speedup vs baseline: 1.0213x; 1.0213x over previous
#include <cuda_runtime.h>
#include <cuda_bf16.h>
#include <cstdint>
#include <cstddef>

namespace {
constexpr int kB    = 128;
constexpr int kT    = 65536;
constexpr int kE    = 512;
constexpr int kSmax = 512;

constexpr int BM = 128;
constexpr int BN = 128;
constexpr int KC = 32;          // k-chunk (floats)

constexpr int NTHREADS = 256;   // 8 warps: 4(m) x 2(n), warp tile 32x64

constexpr int LDSF = 36;        // smem row stride in floats (4r+c bank map, conflict-free)

// float-unit offsets within one buffer
constexpr int OFF_A = 0;                         // 128 x 36
constexpr int OFF_B = BM * LDSF;                 // 4608
constexpr int BUF_FLOATS = OFF_B + BN * LDSF;    // 9216
constexpr int SMEM_FLOATS = 2 * BUF_FLOATS;      // 18432
constexpr int SMEM_BYTES  = SMEM_FLOATS * 4;     // 73728
}

__device__ int g_nvalid[kB];
__device__ int g_cnt[kB];
__device__ int g_done[kB];

// ---------------------------------------------------------------------------
__device__ __forceinline__ uint32_t smem_u32(const void* p) {
    uint32_t a;
    asm("{ .reg .u64 t; cvta.to.shared.u64 t, %1; cvt.u32.u64 %0, t; }" : "=r"(a) : "l"(p));
    return a;
}

__device__ __forceinline__ uint32_t f2tf32(uint32_t x) {
    uint32_t r;
    asm("cvt.rna.tf32.f32 %0, %1;" : "=r"(r) : "r"(x));
    return r;
}

__device__ __forceinline__ void mma_tf32(float* c, const uint32_t* a, const uint32_t* b) {
    asm volatile(
        "mma.sync.aligned.m16n8k8.row.col.f32.tf32.tf32.f32 "
        "{%0,%1,%2,%3}, {%4,%5,%6,%7}, {%8,%9}, {%0,%1,%2,%3};"
        : "+f"(c[0]), "+f"(c[1]), "+f"(c[2]), "+f"(c[3])
        : "r"(a[0]), "r"(a[1]), "r"(a[2]), "r"(a[3]), "r"(b[0]), "r"(b[1]));
}

__device__ __forceinline__ void cp_async16(uint32_t dst, const void* src) {
    asm volatile("cp.async.ca.shared.global [%0], [%1], 16;" :: "r"(dst), "l"(src));
}
__device__ __forceinline__ void cp_commit() {
    asm volatile("cp.async.commit_group;" ::: "memory");
}
template <int N>
__device__ __forceinline__ void cp_wait() {
    asm volatile("cp.async.wait_group %0;" :: "n"(N) : "memory");
}

// ---------------------------------------------------------------------------
// Kernel A: 16 blocks/sample popcount, atomic reduce; last block finalizes.
// ---------------------------------------------------------------------------
__global__ __launch_bounds__(256) void len_mask_kernel(
    const int* __restrict__ mask,
    const int* __restrict__ branch_idx,
    float* __restrict__ out,
    int write_mask)
{
    const int b = blockIdx.x >> 4;
    const int q = blockIdx.x & 15;
    const int t = threadIdx.x;

    const uint4* p = reinterpret_cast<const uint4*>(mask + (size_t)b * kT) + q * 1024;
    int sum = 0;
#pragma unroll 4
    for (int i = t; i < 1024; i += 256) {
        uint4 v = p[i];
        sum += (int)((v.x & 1u) + (v.y & 1u) + (v.z & 1u) + (v.w & 1u));
    }
#pragma unroll
    for (int o = 16; o > 0; o >>= 1) sum += __shfl_down_sync(0xffffffffu, sum, o);

    __shared__ int warp_sums[8];
    __shared__ int is_last;
    if ((t & 31) == 0) warp_sums[t >> 5] = sum;
    __syncthreads();
    if (t == 0) {
        int tot = 0;
#pragma unroll
        for (int i = 0; i < 8; i++) tot += warp_sums[i];
        atomicAdd(&g_cnt[b], tot);
        __threadfence();
        int old = atomicAdd(&g_done[b], 1);
        is_last = (old == 15);
    }
    __syncthreads();

    if (!is_last) return;

    __shared__ int nv_sh;
    if (t == 0) {
        __threadfence();
        int tot = atomicAdd(&g_cnt[b], 0);
        int bi = branch_idx[b];
        int w  = 128 << bi;
        int Sb = kT / w;
        int nv = tot / w;
        if (nv > Sb) nv = Sb;
        g_nvalid[b] = nv;
        nv_sh = nv;
        g_cnt[b]  = 0;
        g_done[b] = 0;
    }
    __syncthreads();

    if (write_mask) {
        int nv = nv_sh;
        float* mout = out + (size_t)kB * kSmax * kE + (size_t)b * kSmax;
        for (int s = t; s < kSmax; s += 256) mout[s] = (s < nv) ? 1.0f : 0.0f;
    }
}

// ---------------------------------------------------------------------------
// Kernel B: tf32 mma.sync GEMM, warp tile 32x64, cp.async double buffer.
// 256 threads, CTA tile 128x128, 2 CTAs/SM. Grid (4, 4, 128).
// ---------------------------------------------------------------------------
__global__ __launch_bounds__(NTHREADS, 2) void branch_gemm_mma(
    const float* __restrict__ signal,
    const int*   __restrict__ branch_idx,
    const float* __restrict__ W0, const float* __restrict__ b0,
    const float* __restrict__ W1, const float* __restrict__ b1,
    const float* __restrict__ W2, const float* __restrict__ b2,
    float* __restrict__ out)
{
    extern __shared__ float smemf[];
    const int tid  = threadIdx.x;
    const int b    = blockIdx.z;
    const int m0   = blockIdx.y * BM;
    const int n0   = blockIdx.x * BN;

    float* outb = out + (size_t)b * kSmax * kE;
    const int nv = g_nvalid[b];

    if (m0 >= nv) {
        float4 z = make_float4(0.f, 0.f, 0.f, 0.f);
#pragma unroll
        for (int i = 0; i < 16; i++) {
            int u   = tid + i * NTHREADS;     // 4096 float4 = 128x128 floats
            int row = u >> 5;
            int c4  = (u & 31) << 2;
            *reinterpret_cast<float4*>(outb + (size_t)(m0 + row) * kE + n0 + c4) = z;
        }
        return;
    }

    const int bi   = branch_idx[b];
    const int logw = 7 + bi;
    const int nchunks = (1 << logw) / KC;     // 4, 8, 16
    const float* Wp = (bi == 0) ? W0 : (bi == 1) ? W1 : W2;
    const float* bp = (bi == 0) ? b0 : (bi == 1) ? b1 : b2;
    const float* Asrc = signal + (size_t)b * kT + ((size_t)m0 << logw);
    const float* Bsrc = Wp + ((size_t)n0 << logw);

    const uint32_t sbase = smem_u32(smemf);
    const int lane   = tid & 31;
    const int warp   = tid >> 5;
    const int warp_m = warp & 3;        // m offset *32
    const int warp_n = warp >> 2;       // n offset *64
    const int g      = lane >> 2;       // 0..7
    const int tg     = lane & 3;

    // fragment bases (float units within a buffer)
    const uint32_t aBase = OFF_A + (warp_m * 32 + g) * LDSF + tg;
    const uint32_t bBase = OFF_B + (warp_n * 64 + g) * LDSF + tg;

    float acc[2][8][4];
#pragma unroll
    for (int mi = 0; mi < 2; mi++)
#pragma unroll
        for (int nj = 0; nj < 8; nj++)
#pragma unroll
            for (int q = 0; q < 4; q++) acc[mi][nj][q] = 0.f;

    // loader: 8 threads/row (32 floats), row = u>>3, c4 = (u&7)*4; 4 iters each for A,B
    const int lrow = tid >> 3;
    const int lc4  = (tid & 7) << 2;

    // prologue: cp.async chunk 0 -> buffer 0
    {
        uint32_t dA = sbase + (OFF_A + lrow * LDSF + lc4) * 4;
        uint32_t dB = sbase + (OFF_B + lrow * LDSF + lc4) * 4;
#pragma unroll
        for (int i = 0; i < 4; i++) {
            int row = lrow + i * 32;
            cp_async16(dA + i * 32 * LDSF * 4, Asrc + ((size_t)row << logw) + lc4);
            cp_async16(dB + i * 32 * LDSF * 4, Bsrc + ((size_t)row << logw) + lc4);
        }
        cp_commit();
    }

    for (int c = 0; c < nchunks; c++) {
        const int cbuf = (c & 1) * BUF_FLOATS;
        const bool more = (c + 1 < nchunks);

        if (more) {
            const int kk = (c + 1) * KC;
            const uint32_t nb = ((c + 1) & 1) * BUF_FLOATS * 4;
            uint32_t dA = sbase + nb + (OFF_A + lrow * LDSF + lc4) * 4;
            uint32_t dB = sbase + nb + (OFF_B + lrow * LDSF + lc4) * 4;
#pragma unroll
            for (int i = 0; i < 4; i++) {
                int row = lrow + i * 32;
                cp_async16(dA + i * 32 * LDSF * 4, Asrc + ((size_t)row << logw) + kk + lc4);
                cp_async16(dB + i * 32 * LDSF * 4, Bsrc + ((size_t)row << logw) + kk + lc4);
            }
            cp_commit();
            cp_wait<1>();
        } else {
            cp_wait<0>();
        }
        __syncthreads();

        // compute chunk c: 4 k8 steps, 16 MMAs each
        const uint32_t* sm = reinterpret_cast<const uint32_t*>(smemf) + cbuf;
#pragma unroll
        for (int s = 0; s < 4; s++) {
            const uint32_t ko = s * 8;
            uint32_t af[2][4], bf[8][2];
#pragma unroll
            for (int mi = 0; mi < 2; mi++) {
                uint32_t base = aBase + mi * 16 * LDSF + ko;
                af[mi][0] = f2tf32(sm[base]);
                af[mi][1] = f2tf32(sm[base + 8 * LDSF]);
                af[mi][2] = f2tf32(sm[base + 4]);
                af[mi][3] = f2tf32(sm[base + 8 * LDSF + 4]);
            }
#pragma unroll
            for (int nj = 0; nj < 8; nj++) {
                uint32_t base = bBase + nj * 8 * LDSF + ko;
                bf[nj][0] = f2tf32(sm[base]);
                bf[nj][1] = f2tf32(sm[base + 4]);
            }
#pragma unroll
            for (int mi = 0; mi < 2; mi++)
#pragma unroll
                for (int nj = 0; nj < 8; nj++)
                    mma_tf32(acc[mi][nj], af[mi], bf[nj]);
        }
        __syncthreads();    // compute done before this buffer is refilled
    }

    // Epilogue
    const int col0 = tg * 2;
    const int rbase = m0 + warp_m * 32 + g;
    const int ncol  = n0 + warp_n * 64;
#pragma unroll
    for (int mi = 0; mi < 2; mi++) {
        int r0 = rbase + mi * 16;
        int r1 = r0 + 8;
        bool v0 = r0 < nv, v1 = r1 < nv;
        float* o0p = outb + (size_t)r0 * kE + ncol + col0;
        float* o1p = outb + (size_t)r1 * kE + ncol + col0;
#pragma unroll
        for (int nj = 0; nj < 8; nj++) {
            float2 bias = *reinterpret_cast<const float2*>(bp + ncol + nj * 8 + col0);
            float2 o0 = v0 ? make_float2(acc[mi][nj][0] + bias.x, acc[mi][nj][1] + bias.y)
                           : make_float2(0.f, 0.f);
            float2 o1 = v1 ? make_float2(acc[mi][nj][2] + bias.x, acc[mi][nj][3] + bias.y)
                           : make_float2(0.f, 0.f);
            *reinterpret_cast<float2*>(o0p + nj * 8) = o0;
            *reinterpret_cast<float2*>(o1p + nj * 8) = o1;
        }
    }
}

// ---------------------------------------------------------------------------
extern "C" void kernel_launch(void* const* d_in, const int* in_sizes, int n_in,
                              void* d_out, int out_size)
{
    const float* signal = (const float*)d_in[0];
    const int*   mask   = (const int*)d_in[1];
    const int*   bidx   = (const int*)d_in[2];
    const float* W0 = (const float*)d_in[3];
    const float* b0 = (const float*)d_in[4];
    const float* W1 = (const float*)d_in[5];
    const float* b1 = (const float*)d_in[6];
    const float* W2 = (const float*)d_in[7];
    const float* b2 = (const float*)d_in[8];
    float* out = (float*)d_out;

    int write_mask = (out_size > kB * kSmax * kE) ? 1 : 0;

    len_mask_kernel<<<kB * 16, 256>>>(mask, bidx, out, write_mask);

    static bool attr_set = false;
    if (!attr_set) {
        cudaFuncSetAttribute(branch_gemm_mma,
                             cudaFuncAttributeMaxDynamicSharedMemorySize, SMEM_BYTES);
        attr_set = true;
    }
    dim3 grid(kE / BN, kSmax / BM, kB);
    branch_gemm_mma<<<grid, NTHREADS, SMEM_BYTES>>>(signal, bidx, W0, b0, W1, b1, W2, b2, out);
}

// round 12
// speedup vs baseline: 1.0427x; 1.0209x over previous
#include <cuda_runtime.h>
#include <cuda_bf16.h>
#include <cstdint>
#include <cstddef>

namespace {
constexpr int kB    = 128;
constexpr int kT    = 65536;
constexpr int kE    = 512;
constexpr int kSmax = 512;

constexpr int BM = 128;
constexpr int BN = 128;
constexpr int KC = 32;          // k-chunk (floats)

constexpr int NTHREADS = 256;   // 8 warps: 4(m) x 2(n), warp tile 32x64

constexpr int LDSF = 36;        // smem row stride in floats

constexpr int OFF_A = 0;                         // 128 x 36
constexpr int OFF_B = BM * LDSF;                 // 4608
constexpr int BUF_FLOATS = OFF_B + BN * LDSF;    // 9216
constexpr int SMEM_FLOATS = 2 * BUF_FLOATS;      // 18432
constexpr int SMEM_BYTES  = SMEM_FLOATS * 4;     // 73728
}

__device__ int g_nvalid[kB];
__device__ int g_cnt[kB];
__device__ int g_done[kB];

// ---------------------------------------------------------------------------
__device__ __forceinline__ uint32_t smem_u32(const void* p) {
    uint32_t a;
    asm("{ .reg .u64 t; cvta.to.shared.u64 t, %1; cvt.u32.u64 %0, t; }" : "=r"(a) : "l"(p));
    return a;
}

__device__ __forceinline__ uint32_t f2tf32(uint32_t x) {
    uint32_t r;
    asm("cvt.rna.tf32.f32 %0, %1;" : "=r"(r) : "r"(x));
    return r;
}

__device__ __forceinline__ void ldsm_x4(uint32_t& r0, uint32_t& r1, uint32_t& r2,
                                        uint32_t& r3, uint32_t addr) {
    asm volatile("ldmatrix.sync.aligned.m8n8.x4.shared.b16 {%0,%1,%2,%3}, [%4];"
                 : "=r"(r0), "=r"(r1), "=r"(r2), "=r"(r3) : "r"(addr));
}

__device__ __forceinline__ void mma_tf32(float* c, const uint32_t* a, const uint32_t* b) {
    asm volatile(
        "mma.sync.aligned.m16n8k8.row.col.f32.tf32.tf32.f32 "
        "{%0,%1,%2,%3}, {%4,%5,%6,%7}, {%8,%9}, {%0,%1,%2,%3};"
        : "+f"(c[0]), "+f"(c[1]), "+f"(c[2]), "+f"(c[3])
        : "r"(a[0]), "r"(a[1]), "r"(a[2]), "r"(a[3]), "r"(b[0]), "r"(b[1]));
}

__device__ __forceinline__ void cp_async16(uint32_t dst, const void* src) {
    asm volatile("cp.async.ca.shared.global [%0], [%1], 16;" :: "r"(dst), "l"(src));
}
__device__ __forceinline__ void cp_commit() {
    asm volatile("cp.async.commit_group;" ::: "memory");
}
template <int N>
__device__ __forceinline__ void cp_wait() {
    asm volatile("cp.async.wait_group %0;" :: "n"(N) : "memory");
}

// ---------------------------------------------------------------------------
// Kernel A: 16 blocks/sample popcount, atomic reduce; last block finalizes.
// ---------------------------------------------------------------------------
__global__ __launch_bounds__(256) void len_mask_kernel(
    const int* __restrict__ mask,
    const int* __restrict__ branch_idx,
    float* __restrict__ out,
    int write_mask)
{
    const int b = blockIdx.x >> 4;
    const int q = blockIdx.x & 15;
    const int t = threadIdx.x;

    const uint4* p = reinterpret_cast<const uint4*>(mask + (size_t)b * kT) + q * 1024;
    int sum = 0;
#pragma unroll 4
    for (int i = t; i < 1024; i += 256) {
        uint4 v = p[i];
        sum += (int)((v.x & 1u) + (v.y & 1u) + (v.z & 1u) + (v.w & 1u));
    }
#pragma unroll
    for (int o = 16; o > 0; o >>= 1) sum += __shfl_down_sync(0xffffffffu, sum, o);

    __shared__ int warp_sums[8];
    __shared__ int is_last;
    if ((t & 31) == 0) warp_sums[t >> 5] = sum;
    __syncthreads();
    if (t == 0) {
        int tot = 0;
#pragma unroll
        for (int i = 0; i < 8; i++) tot += warp_sums[i];
        atomicAdd(&g_cnt[b], tot);
        __threadfence();
        int old = atomicAdd(&g_done[b], 1);
        is_last = (old == 15);
    }
    __syncthreads();

    if (!is_last) return;

    __shared__ int nv_sh;
    if (t == 0) {
        __threadfence();
        int tot = atomicAdd(&g_cnt[b], 0);
        int bi = branch_idx[b];
        int w  = 128 << bi;
        int Sb = kT / w;
        int nv = tot / w;
        if (nv > Sb) nv = Sb;
        g_nvalid[b] = nv;
        nv_sh = nv;
        g_cnt[b]  = 0;
        g_done[b] = 0;
    }
    __syncthreads();

    if (write_mask) {
        int nv = nv_sh;
        float* mout = out + (size_t)kB * kSmax * kE + (size_t)b * kSmax;
        for (int s = t; s < kSmax; s += 256) mout[s] = (s < nv) ? 1.0f : 0.0f;
    }
}

// ---------------------------------------------------------------------------
// Kernel B: tf32 mma.sync GEMM, ldmatrix fragment loads, cp.async double
// buffer. 256 threads, CTA tile 128x128, 2 CTAs/SM. Grid (4, 4, 128).
// ---------------------------------------------------------------------------
__global__ __launch_bounds__(NTHREADS, 2) void branch_gemm_mma(
    const float* __restrict__ signal,
    const int*   __restrict__ branch_idx,
    const float* __restrict__ W0, const float* __restrict__ b0,
    const float* __restrict__ W1, const float* __restrict__ b1,
    const float* __restrict__ W2, const float* __restrict__ b2,
    float* __restrict__ out)
{
    extern __shared__ float smemf[];
    const int tid  = threadIdx.x;
    const int b    = blockIdx.z;
    const int m0   = blockIdx.y * BM;
    const int n0   = blockIdx.x * BN;

    float* outb = out + (size_t)b * kSmax * kE;
    const int nv = g_nvalid[b];

    if (m0 >= nv) {
        float4 z = make_float4(0.f, 0.f, 0.f, 0.f);
#pragma unroll
        for (int i = 0; i < 16; i++) {
            int u   = tid + i * NTHREADS;
            int row = u >> 5;
            int c4  = (u & 31) << 2;
            *reinterpret_cast<float4*>(outb + (size_t)(m0 + row) * kE + n0 + c4) = z;
        }
        return;
    }

    const int bi   = branch_idx[b];
    const int logw = 7 + bi;
    const int nchunks = (1 << logw) / KC;     // 4, 8, 16
    const float* Wp = (bi == 0) ? W0 : (bi == 1) ? W1 : W2;
    const float* bp = (bi == 0) ? b0 : (bi == 1) ? b1 : b2;
    const float* Asrc = signal + (size_t)b * kT + ((size_t)m0 << logw);
    const float* Bsrc = Wp + ((size_t)n0 << logw);

    const uint32_t sbase = smem_u32(smemf);
    const int lane   = tid & 31;
    const int warp   = tid >> 5;
    const int warp_m = warp & 3;        // m offset *32
    const int warp_n = warp >> 2;       // n offset *64
    const int g      = lane >> 2;       // 0..7
    const int tg     = lane & 3;

    // ldmatrix lane addresses (byte offsets within a buffer)
    const int grp = lane >> 3;          // 0..3
    const int r8  = lane & 7;
    // A tiles: rows(0-7 / 8-15) x kcols(0-3 / 4-7):
    //   rowoff = 8*(grp&1), coloff = 4*(grp>>1)
    const uint32_t aRowBase = warp_m * 32 + (grp & 1) * 8 + r8;
    const uint32_t aColOff  = (grp >> 1) * 4;
    const uint32_t aAddr0 = sbase + (OFF_A + aRowBase * LDSF + aColOff) * 4;   // + mi*16*LDSF*4 + s*32
    // B tiles: nrows(0-7 / 8-15) x kcols(0-3 / 4-7):
    //   rowoff = 8*(grp>>1), coloff = 4*(grp&1)
    const uint32_t bRowBase = warp_n * 64 + (grp >> 1) * 8 + r8;
    const uint32_t bColOff  = (grp & 1) * 4;
    const uint32_t bAddr0 = sbase + (OFF_B + bRowBase * LDSF + bColOff) * 4;   // + q*16*LDSF*4 + s*32

    float acc[2][8][4];
#pragma unroll
    for (int mi = 0; mi < 2; mi++)
#pragma unroll
        for (int nj = 0; nj < 8; nj++)
#pragma unroll
            for (int q = 0; q < 4; q++) acc[mi][nj][q] = 0.f;

    // cp.async loader: 8 threads/row (32 floats)
    const int lrow = tid >> 3;
    const int lc4  = (tid & 7) << 2;

    {
        uint32_t dA = sbase + (OFF_A + lrow * LDSF + lc4) * 4;
        uint32_t dB = sbase + (OFF_B + lrow * LDSF + lc4) * 4;
#pragma unroll
        for (int i = 0; i < 4; i++) {
            int row = lrow + i * 32;
            cp_async16(dA + i * 32 * LDSF * 4, Asrc + ((size_t)row << logw) + lc4);
            cp_async16(dB + i * 32 * LDSF * 4, Bsrc + ((size_t)row << logw) + lc4);
        }
        cp_commit();
    }

    for (int c = 0; c < nchunks; c++) {
        const uint32_t cbufB = (c & 1) * BUF_FLOATS * 4;
        const bool more = (c + 1 < nchunks);

        if (more) {
            const int kk = (c + 1) * KC;
            const uint32_t nb = ((c + 1) & 1) * BUF_FLOATS * 4;
            uint32_t dA = sbase + nb + (OFF_A + lrow * LDSF + lc4) * 4;
            uint32_t dB = sbase + nb + (OFF_B + lrow * LDSF + lc4) * 4;
#pragma unroll
            for (int i = 0; i < 4; i++) {
                int row = lrow + i * 32;
                cp_async16(dA + i * 32 * LDSF * 4, Asrc + ((size_t)row << logw) + kk + lc4);
                cp_async16(dB + i * 32 * LDSF * 4, Bsrc + ((size_t)row << logw) + kk + lc4);
            }
            cp_commit();
            cp_wait<1>();
        } else {
            cp_wait<0>();
        }
        __syncthreads();

        // compute chunk c: 4 k8 steps, 16 MMAs each; ldmatrix fragment loads
#pragma unroll
        for (int s = 0; s < 4; s++) {
            const uint32_t ks = cbufB + s * 32;
            uint32_t af[2][4], bf[8][2];
#pragma unroll
            for (int mi = 0; mi < 2; mi++) {
                uint32_t r0, r1, r2, r3;
                ldsm_x4(r0, r1, r2, r3, aAddr0 + ks + mi * (16 * LDSF * 4));
                af[mi][0] = f2tf32(r0);
                af[mi][1] = f2tf32(r1);
                af[mi][2] = f2tf32(r2);
                af[mi][3] = f2tf32(r3);
            }
#pragma unroll
            for (int q = 0; q < 4; q++) {
                uint32_t r0, r1, r2, r3;
                ldsm_x4(r0, r1, r2, r3, bAddr0 + ks + q * (16 * LDSF * 4));
                bf[2 * q][0]     = f2tf32(r0);
                bf[2 * q][1]     = f2tf32(r1);
                bf[2 * q + 1][0] = f2tf32(r2);
                bf[2 * q + 1][1] = f2tf32(r3);
            }
#pragma unroll
            for (int mi = 0; mi < 2; mi++)
#pragma unroll
                for (int nj = 0; nj < 8; nj++)
                    mma_tf32(acc[mi][nj], af[mi], bf[nj]);
        }
        __syncthreads();
    }

    // Epilogue
    const int col0 = tg * 2;
    const int rbase = m0 + warp_m * 32 + g;
    const int ncol  = n0 + warp_n * 64;
#pragma unroll
    for (int mi = 0; mi < 2; mi++) {
        int r0 = rbase + mi * 16;
        int r1 = r0 + 8;
        bool v0 = r0 < nv, v1 = r1 < nv;
        float* o0p = outb + (size_t)r0 * kE + ncol + col0;
        float* o1p = outb + (size_t)r1 * kE + ncol + col0;
#pragma unroll
        for (int nj = 0; nj < 8; nj++) {
            float2 bias = *reinterpret_cast<const float2*>(bp + ncol + nj * 8 + col0);
            float2 o0 = v0 ? make_float2(acc[mi][nj][0] + bias.x, acc[mi][nj][1] + bias.y)
                           : make_float2(0.f, 0.f);
            float2 o1 = v1 ? make_float2(acc[mi][nj][2] + bias.x, acc[mi][nj][3] + bias.y)
                           : make_float2(0.f, 0.f);
            *reinterpret_cast<float2*>(o0p + nj * 8) = o0;
            *reinterpret_cast<float2*>(o1p + nj * 8) = o1;
        }
    }
}

// ---------------------------------------------------------------------------
extern "C" void kernel_launch(void* const* d_in, const int* in_sizes, int n_in,
                              void* d_out, int out_size)
{
    const float* signal = (const float*)d_in[0];
    const int*   mask   = (const int*)d_in[1];
    const int*   bidx   = (const int*)d_in[2];
    const float* W0 = (const float*)d_in[3];
    const float* b0 = (const float*)d_in[4];
    const float* W1 = (const float*)d_in[5];
    const float* b1 = (const float*)d_in[6];
    const float* W2 = (const float*)d_in[7];
    const float* b2 = (const float*)d_in[8];
    float* out = (float*)d_out;

    int write_mask = (out_size > kB * kSmax * kE) ? 1 : 0;

    len_mask_kernel<<<kB * 16, 256>>>(mask, bidx, out, write_mask);

    static bool attr_set = false;
    if (!attr_set) {
        cudaFuncSetAttribute(branch_gemm_mma,
                             cudaFuncAttributeMaxDynamicSharedMemorySize, SMEM_BYTES);
        attr_set = true;
    }
    dim3 grid(kE / BN, kSmax / BM, kB);
    branch_gemm_mma<<<grid, NTHREADS, SMEM_BYTES>>>(signal, bidx, W0, b0, W1, b1, W2, b2, out);
}

// round 13
// speedup vs baseline: 1.1490x; 1.1020x over previous
#include <cuda_runtime.h>
#include <cuda_bf16.h>
#include <cstdint>
#include <cstddef>

namespace {
constexpr int kB    = 128;
constexpr int kT    = 65536;
constexpr int kE    = 512;
constexpr int kSmax = 512;

constexpr int BM = 64;
constexpr int BN = 128;
constexpr int KC = 32;          // k-chunk (floats)

constexpr int NTHREADS = 128;   // 4 warps: 2(m) x 2(n), warp tile 32x64

constexpr int LDSF = 36;        // smem row stride in floats

constexpr int OFF_A = 0;                         // 64 x 36
constexpr int OFF_B = BM * LDSF;                 // 2304
constexpr int BUF_FLOATS = OFF_B + BN * LDSF;    // 6912
constexpr int SMEM_FLOATS = 2 * BUF_FLOATS;      // 13824
constexpr int SMEM_BYTES  = SMEM_FLOATS * 4;     // 55296
}

__device__ int g_nvalid[kB];
__device__ int g_cnt[kB];
__device__ int g_done[kB];

// ---------------------------------------------------------------------------
__device__ __forceinline__ uint32_t smem_u32(const void* p) {
    uint32_t a;
    asm("{ .reg .u64 t; cvta.to.shared.u64 t, %1; cvt.u32.u64 %0, t; }" : "=r"(a) : "l"(p));
    return a;
}

__device__ __forceinline__ uint32_t f2tf32(uint32_t x) {
    uint32_t r;
    asm("cvt.rna.tf32.f32 %0, %1;" : "=r"(r) : "r"(x));
    return r;
}

__device__ __forceinline__ void ldsm_x4(uint32_t& r0, uint32_t& r1, uint32_t& r2,
                                        uint32_t& r3, uint32_t addr) {
    asm volatile("ldmatrix.sync.aligned.m8n8.x4.shared.b16 {%0,%1,%2,%3}, [%4];"
                 : "=r"(r0), "=r"(r1), "=r"(r2), "=r"(r3) : "r"(addr));
}

__device__ __forceinline__ void mma_tf32(float* c, const uint32_t* a, const uint32_t* b) {
    asm volatile(
        "mma.sync.aligned.m16n8k8.row.col.f32.tf32.tf32.f32 "
        "{%0,%1,%2,%3}, {%4,%5,%6,%7}, {%8,%9}, {%0,%1,%2,%3};"
        : "+f"(c[0]), "+f"(c[1]), "+f"(c[2]), "+f"(c[3])
        : "r"(a[0]), "r"(a[1]), "r"(a[2]), "r"(a[3]), "r"(b[0]), "r"(b[1]));
}

__device__ __forceinline__ void cp_async16(uint32_t dst, const void* src) {
    asm volatile("cp.async.ca.shared.global [%0], [%1], 16;" :: "r"(dst), "l"(src));
}
__device__ __forceinline__ void cp_commit() {
    asm volatile("cp.async.commit_group;" ::: "memory");
}
template <int N>
__device__ __forceinline__ void cp_wait() {
    asm volatile("cp.async.wait_group %0;" :: "n"(N) : "memory");
}

// ---------------------------------------------------------------------------
// Kernel A: 16 blocks/sample popcount, atomic reduce; last block finalizes.
// ---------------------------------------------------------------------------
__global__ __launch_bounds__(256) void len_mask_kernel(
    const int* __restrict__ mask,
    const int* __restrict__ branch_idx,
    float* __restrict__ out,
    int write_mask)
{
    const int b = blockIdx.x >> 4;
    const int q = blockIdx.x & 15;
    const int t = threadIdx.x;

    const uint4* p = reinterpret_cast<const uint4*>(mask + (size_t)b * kT) + q * 1024;
    int sum = 0;
#pragma unroll 4
    for (int i = t; i < 1024; i += 256) {
        uint4 v = p[i];
        sum += (int)((v.x & 1u) + (v.y & 1u) + (v.z & 1u) + (v.w & 1u));
    }
#pragma unroll
    for (int o = 16; o > 0; o >>= 1) sum += __shfl_down_sync(0xffffffffu, sum, o);

    __shared__ int warp_sums[8];
    __shared__ int is_last;
    if ((t & 31) == 0) warp_sums[t >> 5] = sum;
    __syncthreads();
    if (t == 0) {
        int tot = 0;
#pragma unroll
        for (int i = 0; i < 8; i++) tot += warp_sums[i];
        atomicAdd(&g_cnt[b], tot);
        __threadfence();
        int old = atomicAdd(&g_done[b], 1);
        is_last = (old == 15);
    }
    __syncthreads();

    if (!is_last) return;

    __shared__ int nv_sh;
    if (t == 0) {
        __threadfence();
        int tot = atomicAdd(&g_cnt[b], 0);
        int bi = branch_idx[b];
        int w  = 128 << bi;
        int Sb = kT / w;
        int nv = tot / w;
        if (nv > Sb) nv = Sb;
        g_nvalid[b] = nv;
        nv_sh = nv;
        g_cnt[b]  = 0;
        g_done[b] = 0;
    }
    __syncthreads();

    if (write_mask) {
        int nv = nv_sh;
        float* mout = out + (size_t)kB * kSmax * kE + (size_t)b * kSmax;
        for (int s = t; s < kSmax; s += 256) mout[s] = (s < nv) ? 1.0f : 0.0f;
    }
}

// ---------------------------------------------------------------------------
// Kernel B: tf32 mma.sync GEMM. CTA tile 64x128, 4 warps (32x64 each),
// ldmatrix + cp.async double buffer, 4 CTAs/SM. Grid (4, 8, 128).
// ---------------------------------------------------------------------------
__global__ __launch_bounds__(NTHREADS, 4) void branch_gemm_mma(
    const float* __restrict__ signal,
    const int*   __restrict__ branch_idx,
    const float* __restrict__ W0, const float* __restrict__ b0,
    const float* __restrict__ W1, const float* __restrict__ b1,
    const float* __restrict__ W2, const float* __restrict__ b2,
    float* __restrict__ out)
{
    extern __shared__ float smemf[];
    const int tid  = threadIdx.x;
    const int b    = blockIdx.z;
    const int m0   = blockIdx.y * BM;
    const int n0   = blockIdx.x * BN;

    float* outb = out + (size_t)b * kSmax * kE;
    const int nv = g_nvalid[b];

    if (m0 >= nv) {
        float4 z = make_float4(0.f, 0.f, 0.f, 0.f);
#pragma unroll
        for (int i = 0; i < 16; i++) {
            int u   = tid + i * NTHREADS;     // 2048 float4 = 64x128 floats
            int row = u >> 5;
            int c4  = (u & 31) << 2;
            *reinterpret_cast<float4*>(outb + (size_t)(m0 + row) * kE + n0 + c4) = z;
        }
        return;
    }

    const int bi   = branch_idx[b];
    const int logw = 7 + bi;
    const int nchunks = (1 << logw) / KC;     // 4, 8, 16
    const float* Wp = (bi == 0) ? W0 : (bi == 1) ? W1 : W2;
    const float* bp = (bi == 0) ? b0 : (bi == 1) ? b1 : b2;
    const float* Asrc = signal + (size_t)b * kT + ((size_t)m0 << logw);
    const float* Bsrc = Wp + ((size_t)n0 << logw);

    const uint32_t sbase = smem_u32(smemf);
    const int lane   = tid & 31;
    const int warp   = tid >> 5;
    const int warp_m = warp & 1;        // m offset *32
    const int warp_n = warp >> 1;       // n offset *64
    const int g      = lane >> 2;       // 0..7
    const int tg     = lane & 3;

    // ldmatrix lane addresses (byte offsets within a buffer)
    const int grp = lane >> 3;          // 0..3
    const int r8  = lane & 7;
    const uint32_t aRowBase = warp_m * 32 + (grp & 1) * 8 + r8;
    const uint32_t aColOff  = (grp >> 1) * 4;
    const uint32_t aAddr0 = sbase + (OFF_A + aRowBase * LDSF + aColOff) * 4;   // + mi*16*LDSF*4 + s*32
    const uint32_t bRowBase = warp_n * 64 + (grp >> 1) * 8 + r8;
    const uint32_t bColOff  = (grp & 1) * 4;
    const uint32_t bAddr0 = sbase + (OFF_B + bRowBase * LDSF + bColOff) * 4;   // + q*16*LDSF*4 + s*32

    float acc[2][8][4];
#pragma unroll
    for (int mi = 0; mi < 2; mi++)
#pragma unroll
        for (int nj = 0; nj < 8; nj++)
#pragma unroll
            for (int q = 0; q < 4; q++) acc[mi][nj][q] = 0.f;

    // cp.async loader: 8 threads/row (32 floats), 16 rows per pass
    const int lrow = tid >> 3;          // 0..15
    const int lc4  = (tid & 7) << 2;

    {
        uint32_t dA = sbase + (OFF_A + lrow * LDSF + lc4) * 4;
        uint32_t dB = sbase + (OFF_B + lrow * LDSF + lc4) * 4;
#pragma unroll
        for (int i = 0; i < 4; i++) {   // A: 64 rows
            int row = lrow + i * 16;
            cp_async16(dA + i * 16 * LDSF * 4, Asrc + ((size_t)row << logw) + lc4);
        }
#pragma unroll
        for (int i = 0; i < 8; i++) {   // B: 128 rows
            int row = lrow + i * 16;
            cp_async16(dB + i * 16 * LDSF * 4, Bsrc + ((size_t)row << logw) + lc4);
        }
        cp_commit();
    }

    for (int c = 0; c < nchunks; c++) {
        const uint32_t cbufB = (c & 1) * BUF_FLOATS * 4;
        const bool more = (c + 1 < nchunks);

        if (more) {
            const int kk = (c + 1) * KC;
            const uint32_t nb = ((c + 1) & 1) * BUF_FLOATS * 4;
            uint32_t dA = sbase + nb + (OFF_A + lrow * LDSF + lc4) * 4;
            uint32_t dB = sbase + nb + (OFF_B + lrow * LDSF + lc4) * 4;
#pragma unroll
            for (int i = 0; i < 4; i++) {
                int row = lrow + i * 16;
                cp_async16(dA + i * 16 * LDSF * 4, Asrc + ((size_t)row << logw) + kk + lc4);
            }
#pragma unroll
            for (int i = 0; i < 8; i++) {
                int row = lrow + i * 16;
                cp_async16(dB + i * 16 * LDSF * 4, Bsrc + ((size_t)row << logw) + kk + lc4);
            }
            cp_commit();
            cp_wait<1>();
        } else {
            cp_wait<0>();
        }
        __syncthreads();

        // compute chunk c: 4 k8 steps, 16 MMAs each
#pragma unroll
        for (int s = 0; s < 4; s++) {
            const uint32_t ks = cbufB + s * 32;
            uint32_t af[2][4], bf[8][2];
#pragma unroll
            for (int mi = 0; mi < 2; mi++) {
                uint32_t r0, r1, r2, r3;
                ldsm_x4(r0, r1, r2, r3, aAddr0 + ks + mi * (16 * LDSF * 4));
                af[mi][0] = f2tf32(r0);
                af[mi][1] = f2tf32(r1);
                af[mi][2] = f2tf32(r2);
                af[mi][3] = f2tf32(r3);
            }
#pragma unroll
            for (int q = 0; q < 4; q++) {
                uint32_t r0, r1, r2, r3;
                ldsm_x4(r0, r1, r2, r3, bAddr0 + ks + q * (16 * LDSF * 4));
                bf[2 * q][0]     = f2tf32(r0);
                bf[2 * q][1]     = f2tf32(r1);
                bf[2 * q + 1][0] = f2tf32(r2);
                bf[2 * q + 1][1] = f2tf32(r3);
            }
#pragma unroll
            for (int mi = 0; mi < 2; mi++)
#pragma unroll
                for (int nj = 0; nj < 8; nj++)
                    mma_tf32(acc[mi][nj], af[mi], bf[nj]);
        }
        __syncthreads();
    }

    // Epilogue
    const int col0 = tg * 2;
    const int rbase = m0 + warp_m * 32 + g;
    const int ncol  = n0 + warp_n * 64;
#pragma unroll
    for (int mi = 0; mi < 2; mi++) {
        int r0 = rbase + mi * 16;
        int r1 = r0 + 8;
        bool v0 = r0 < nv, v1 = r1 < nv;
        float* o0p = outb + (size_t)r0 * kE + ncol + col0;
        float* o1p = outb + (size_t)r1 * kE + ncol + col0;
#pragma unroll
        for (int nj = 0; nj < 8; nj++) {
            float2 bias = *reinterpret_cast<const float2*>(bp + ncol + nj * 8 + col0);
            float2 o0 = v0 ? make_float2(acc[mi][nj][0] + bias.x, acc[mi][nj][1] + bias.y)
                           : make_float2(0.f, 0.f);
            float2 o1 = v1 ? make_float2(acc[mi][nj][2] + bias.x, acc[mi][nj][3] + bias.y)
                           : make_float2(0.f, 0.f);
            *reinterpret_cast<float2*>(o0p + nj * 8) = o0;
            *reinterpret_cast<float2*>(o1p + nj * 8) = o1;
        }
    }
}

// ---------------------------------------------------------------------------
extern "C" void kernel_launch(void* const* d_in, const int* in_sizes, int n_in,
                              void* d_out, int out_size)
{
    const float* signal = (const float*)d_in[0];
    const int*   mask   = (const int*)d_in[1];
    const int*   bidx   = (const int*)d_in[2];
    const float* W0 = (const float*)d_in[3];
    const float* b0 = (const float*)d_in[4];
    const float* W1 = (const float*)d_in[5];
    const float* b1 = (const float*)d_in[6];
    const float* W2 = (const float*)d_in[7];
    const float* b2 = (const float*)d_in[8];
    float* out = (float*)d_out;

    int write_mask = (out_size > kB * kSmax * kE) ? 1 : 0;

    len_mask_kernel<<<kB * 16, 256>>>(mask, bidx, out, write_mask);

    static bool attr_set = false;
    if (!attr_set) {
        cudaFuncSetAttribute(branch_gemm_mma,
                             cudaFuncAttributeMaxDynamicSharedMemorySize, SMEM_BYTES);
        attr_set = true;
    }
    dim3 grid(kE / BN, kSmax / BM, kB);
    branch_gemm_mma<<<grid, NTHREADS, SMEM_BYTES>>>(signal, bidx, W0, b0, W1, b1, W2, b2, out);
}

// round 14
// speedup vs baseline: 1.2921x; 1.1246x over previous
#include <cuda_runtime.h>
#include <cuda_bf16.h>
#include <cstdint>
#include <cstddef>

namespace {
constexpr int kB    = 128;
constexpr int kT    = 65536;
constexpr int kE    = 512;
constexpr int kSmax = 512;

constexpr int BM = 64;
constexpr int BN = 128;
constexpr int KC = 32;          // k-chunk (floats)

constexpr int NTHREADS = 128;   // 4 warps: 2(m) x 2(n), warp tile 32x64

constexpr int LDSF = 36;        // smem row stride in floats

constexpr int OFF_A = 0;                         // 64 x 36
constexpr int OFF_B = BM * LDSF;                 // 2304
constexpr int BUF_FLOATS = OFF_B + BN * LDSF;    // 6912
constexpr int SMEM_FLOATS = 2 * BUF_FLOATS;      // 13824
constexpr int SMEM_BYTES  = SMEM_FLOATS * 4;     // 55296
}

__device__ int g_nvalid[kB];
__device__ int g_cnt[kB];
__device__ int g_done[kB];

// ---------------------------------------------------------------------------
__device__ __forceinline__ uint32_t smem_u32(const void* p) {
    uint32_t a;
    asm("{ .reg .u64 t; cvta.to.shared.u64 t, %1; cvt.u32.u64 %0, t; }" : "=r"(a) : "l"(p));
    return a;
}

__device__ __forceinline__ void ldsm_x4(uint32_t& r0, uint32_t& r1, uint32_t& r2,
                                        uint32_t& r3, uint32_t addr) {
    asm volatile("ldmatrix.sync.aligned.m8n8.x4.shared.b16 {%0,%1,%2,%3}, [%4];"
                 : "=r"(r0), "=r"(r1), "=r"(r2), "=r"(r3) : "r"(addr));
}

__device__ __forceinline__ void mma_tf32(float* c, const uint32_t* a, const uint32_t* b) {
    asm volatile(
        "mma.sync.aligned.m16n8k8.row.col.f32.tf32.tf32.f32 "
        "{%0,%1,%2,%3}, {%4,%5,%6,%7}, {%8,%9}, {%0,%1,%2,%3};"
        : "+f"(c[0]), "+f"(c[1]), "+f"(c[2]), "+f"(c[3])
        : "r"(a[0]), "r"(a[1]), "r"(a[2]), "r"(a[3]), "r"(b[0]), "r"(b[1]));
}

__device__ __forceinline__ void cp_async16(uint32_t dst, const void* src) {
    asm volatile("cp.async.cg.shared.global [%0], [%1], 16;" :: "r"(dst), "l"(src));
}
__device__ __forceinline__ void cp_commit() {
    asm volatile("cp.async.commit_group;" ::: "memory");
}
template <int N>
__device__ __forceinline__ void cp_wait() {
    asm volatile("cp.async.wait_group %0;" :: "n"(N) : "memory");
}

// ---------------------------------------------------------------------------
// Kernel A: 32 blocks/sample popcount, atomic reduce; last block finalizes.
// ---------------------------------------------------------------------------
__global__ __launch_bounds__(256) void len_mask_kernel(
    const int* __restrict__ mask,
    const int* __restrict__ branch_idx,
    float* __restrict__ out,
    int write_mask)
{
    const int b = blockIdx.x >> 5;
    const int q = blockIdx.x & 31;
    const int t = threadIdx.x;

    const uint4* p = reinterpret_cast<const uint4*>(mask + (size_t)b * kT) + q * 512;
    int sum = 0;
#pragma unroll 2
    for (int i = t; i < 512; i += 256) {
        uint4 v = p[i];
        sum += (int)((v.x & 1u) + (v.y & 1u) + (v.z & 1u) + (v.w & 1u));
    }
#pragma unroll
    for (int o = 16; o > 0; o >>= 1) sum += __shfl_down_sync(0xffffffffu, sum, o);

    __shared__ int warp_sums[8];
    __shared__ int is_last;
    if ((t & 31) == 0) warp_sums[t >> 5] = sum;
    __syncthreads();
    if (t == 0) {
        int tot = 0;
#pragma unroll
        for (int i = 0; i < 8; i++) tot += warp_sums[i];
        atomicAdd(&g_cnt[b], tot);
        __threadfence();
        int old = atomicAdd(&g_done[b], 1);
        is_last = (old == 31);
    }
    __syncthreads();

    if (!is_last) return;

    __shared__ int nv_sh;
    if (t == 0) {
        __threadfence();
        int tot = atomicAdd(&g_cnt[b], 0);
        int bi = branch_idx[b];
        int w  = 128 << bi;
        int Sb = kT / w;
        int nv = tot / w;
        if (nv > Sb) nv = Sb;
        g_nvalid[b] = nv;
        nv_sh = nv;
        g_cnt[b]  = 0;
        g_done[b] = 0;
    }
    __syncthreads();

    if (write_mask) {
        int nv = nv_sh;
        float* mout = out + (size_t)kB * kSmax * kE + (size_t)b * kSmax;
        for (int s = t; s < kSmax; s += 256) mout[s] = (s < nv) ? 1.0f : 0.0f;
    }
}

// ---------------------------------------------------------------------------
// Kernel B: tf32 mma.sync GEMM (raw-fp32 fast path, no cvt). CTA tile 64x128,
// 4 warps (32x64), ldmatrix + cp.async.cg double buffer, 4 CTAs/SM.
// Grid (4, 8, 128).
// ---------------------------------------------------------------------------
__global__ __launch_bounds__(NTHREADS, 4) void branch_gemm_mma(
    const float* __restrict__ signal,
    const int*   __restrict__ branch_idx,
    const float* __restrict__ W0, const float* __restrict__ b0,
    const float* __restrict__ W1, const float* __restrict__ b1,
    const float* __restrict__ W2, const float* __restrict__ b2,
    float* __restrict__ out)
{
    extern __shared__ float smemf[];
    const int tid  = threadIdx.x;
    const int b    = blockIdx.z;
    const int m0   = blockIdx.y * BM;
    const int n0   = blockIdx.x * BN;

    float* outb = out + (size_t)b * kSmax * kE;
    const int nv = g_nvalid[b];

    if (m0 >= nv) {
        float4 z = make_float4(0.f, 0.f, 0.f, 0.f);
#pragma unroll
        for (int i = 0; i < 16; i++) {
            int u   = tid + i * NTHREADS;     // 2048 float4 = 64x128 floats
            int row = u >> 5;
            int c4  = (u & 31) << 2;
            *reinterpret_cast<float4*>(outb + (size_t)(m0 + row) * kE + n0 + c4) = z;
        }
        return;
    }

    const int bi   = branch_idx[b];
    const int logw = 7 + bi;
    const int nchunks = (1 << logw) / KC;     // 4, 8, 16
    const float* Wp = (bi == 0) ? W0 : (bi == 1) ? W1 : W2;
    const float* bp = (bi == 0) ? b0 : (bi == 1) ? b1 : b2;
    const float* Asrc = signal + (size_t)b * kT + ((size_t)m0 << logw);
    const float* Bsrc = Wp + ((size_t)n0 << logw);

    const uint32_t sbase = smem_u32(smemf);
    const int lane   = tid & 31;
    const int warp   = tid >> 5;
    const int warp_m = warp & 1;        // m offset *32
    const int warp_n = warp >> 1;       // n offset *64
    const int g      = lane >> 2;       // 0..7
    const int tg     = lane & 3;

    // ldmatrix lane addresses (byte offsets within a buffer)
    const int grp = lane >> 3;          // 0..3
    const int r8  = lane & 7;
    const uint32_t aRowBase = warp_m * 32 + (grp & 1) * 8 + r8;
    const uint32_t aColOff  = (grp >> 1) * 4;
    const uint32_t aAddr0 = sbase + (OFF_A + aRowBase * LDSF + aColOff) * 4;
    const uint32_t bRowBase = warp_n * 64 + (grp >> 1) * 8 + r8;
    const uint32_t bColOff  = (grp & 1) * 4;
    const uint32_t bAddr0 = sbase + (OFF_B + bRowBase * LDSF + bColOff) * 4;

    float acc[2][8][4];
#pragma unroll
    for (int mi = 0; mi < 2; mi++)
#pragma unroll
        for (int nj = 0; nj < 8; nj++)
#pragma unroll
            for (int q = 0; q < 4; q++) acc[mi][nj][q] = 0.f;

    // cp.async loader: 8 threads/row (32 floats), 16 rows per pass
    const int lrow = tid >> 3;          // 0..15
    const int lc4  = (tid & 7) << 2;

    {
        uint32_t dA = sbase + (OFF_A + lrow * LDSF + lc4) * 4;
        uint32_t dB = sbase + (OFF_B + lrow * LDSF + lc4) * 4;
#pragma unroll
        for (int i = 0; i < 4; i++) {
            int row = lrow + i * 16;
            cp_async16(dA + i * 16 * LDSF * 4, Asrc + ((size_t)row << logw) + lc4);
        }
#pragma unroll
        for (int i = 0; i < 8; i++) {
            int row = lrow + i * 16;
            cp_async16(dB + i * 16 * LDSF * 4, Bsrc + ((size_t)row << logw) + lc4);
        }
        cp_commit();
    }

    for (int c = 0; c < nchunks; c++) {
        const uint32_t cbufB = (c & 1) * BUF_FLOATS * 4;
        const bool more = (c + 1 < nchunks);

        if (more) {
            const int kk = (c + 1) * KC;
            const uint32_t nb = ((c + 1) & 1) * BUF_FLOATS * 4;
            uint32_t dA = sbase + nb + (OFF_A + lrow * LDSF + lc4) * 4;
            uint32_t dB = sbase + nb + (OFF_B + lrow * LDSF + lc4) * 4;
#pragma unroll
            for (int i = 0; i < 4; i++) {
                int row = lrow + i * 16;
                cp_async16(dA + i * 16 * LDSF * 4, Asrc + ((size_t)row << logw) + kk + lc4);
            }
#pragma unroll
            for (int i = 0; i < 8; i++) {
                int row = lrow + i * 16;
                cp_async16(dB + i * 16 * LDSF * 4, Bsrc + ((size_t)row << logw) + kk + lc4);
            }
            cp_commit();
            cp_wait<1>();
        } else {
            cp_wait<0>();
        }
        __syncthreads();

        // compute chunk c: 4 k8 steps, 16 MMAs each; raw fp32 bits as tf32
        // (CUTLASS round-toward-zero fast path: HMMA reads high 19 bits)
#pragma unroll
        for (int s = 0; s < 4; s++) {
            const uint32_t ks = cbufB + s * 32;
            uint32_t af[2][4], bf[8][2];
#pragma unroll
            for (int mi = 0; mi < 2; mi++) {
                ldsm_x4(af[mi][0], af[mi][1], af[mi][2], af[mi][3],
                        aAddr0 + ks + mi * (16 * LDSF * 4));
            }
#pragma unroll
            for (int q = 0; q < 4; q++) {
                uint32_t r0, r1, r2, r3;
                ldsm_x4(r0, r1, r2, r3, bAddr0 + ks + q * (16 * LDSF * 4));
                bf[2 * q][0]     = r0;
                bf[2 * q][1]     = r1;
                bf[2 * q + 1][0] = r2;
                bf[2 * q + 1][1] = r3;
            }
#pragma unroll
            for (int mi = 0; mi < 2; mi++)
#pragma unroll
                for (int nj = 0; nj < 8; nj++)
                    mma_tf32(acc[mi][nj], af[mi], bf[nj]);
        }
        __syncthreads();
    }

    // Epilogue
    const int col0 = tg * 2;
    const int rbase = m0 + warp_m * 32 + g;
    const int ncol  = n0 + warp_n * 64;
#pragma unroll
    for (int mi = 0; mi < 2; mi++) {
        int r0 = rbase + mi * 16;
        int r1 = r0 + 8;
        bool v0 = r0 < nv, v1 = r1 < nv;
        float* o0p = outb + (size_t)r0 * kE + ncol + col0;
        float* o1p = outb + (size_t)r1 * kE + ncol + col0;
#pragma unroll
        for (int nj = 0; nj < 8; nj++) {
            float2 bias = *reinterpret_cast<const float2*>(bp + ncol + nj * 8 + col0);
            float2 o0 = v0 ? make_float2(acc[mi][nj][0] + bias.x, acc[mi][nj][1] + bias.y)
                           : make_float2(0.f, 0.f);
            float2 o1 = v1 ? make_float2(acc[mi][nj][2] + bias.x, acc[mi][nj][3] + bias.y)
                           : make_float2(0.f, 0.f);
            *reinterpret_cast<float2*>(o0p + nj * 8) = o0;
            *reinterpret_cast<float2*>(o1p + nj * 8) = o1;
        }
    }
}

// ---------------------------------------------------------------------------
extern "C" void kernel_launch(void* const* d_in, const int* in_sizes, int n_in,
                              void* d_out, int out_size)
{
    const float* signal = (const float*)d_in[0];
    const int*   mask   = (const int*)d_in[1];
    const int*   bidx   = (const int*)d_in[2];
    const float* W0 = (const float*)d_in[3];
    const float* b0 = (const float*)d_in[4];
    const float* W1 = (const float*)d_in[5];
    const float* b1 = (const float*)d_in[6];
    const float* W2 = (const float*)d_in[7];
    const float* b2 = (const float*)d_in[8];
    float* out = (float*)d_out;

    int write_mask = (out_size > kB * kSmax * kE) ? 1 : 0;

    len_mask_kernel<<<kB * 32, 256>>>(mask, bidx, out, write_mask);

    static bool attr_set = false;
    if (!attr_set) {
        cudaFuncSetAttribute(branch_gemm_mma,
                             cudaFuncAttributeMaxDynamicSharedMemorySize, SMEM_BYTES);
        attr_set = true;
    }
    dim3 grid(kE / BN, kSmax / BM, kB);
    branch_gemm_mma<<<grid, NTHREADS, SMEM_BYTES>>>(signal, bidx, W0, b0, W1, b1, W2, b2, out);
}

// round 15
// speedup vs baseline: 1.3221x; 1.0232x over previous
#include <cuda_runtime.h>
#include <cuda_bf16.h>
#include <cstdint>
#include <cstddef>

namespace {
constexpr int kB    = 128;
constexpr int kT    = 65536;
constexpr int kE    = 512;
constexpr int kSmax = 512;

constexpr int BM = 64;
constexpr int BN = 128;
constexpr int KC = 32;          // k-chunk (floats)

constexpr int NTHREADS = 128;   // 4 warps: 2(m) x 2(n), warp tile 32x64

constexpr int LDSF = 36;        // smem row stride in floats

constexpr int OFF_A = 0;                         // 64 x 36
constexpr int OFF_B = BM * LDSF;                 // 2304
constexpr int BUF_FLOATS = OFF_B + BN * LDSF;    // 6912
constexpr int SMEM_FLOATS = 2 * BUF_FLOATS;      // 13824
constexpr int SMEM_BYTES  = SMEM_FLOATS * 4;     // 55296
}

__device__ int g_nvalid[kB];
__device__ int g_cnt[kB];
__device__ int g_done[kB];

// ---------------------------------------------------------------------------
__device__ __forceinline__ uint32_t smem_u32(const void* p) {
    uint32_t a;
    asm("{ .reg .u64 t; cvta.to.shared.u64 t, %1; cvt.u32.u64 %0, t; }" : "=r"(a) : "l"(p));
    return a;
}

__device__ __forceinline__ void ldsm_x4(uint32_t& r0, uint32_t& r1, uint32_t& r2,
                                        uint32_t& r3, uint32_t addr) {
    asm volatile("ldmatrix.sync.aligned.m8n8.x4.shared.b16 {%0,%1,%2,%3}, [%4];"
                 : "=r"(r0), "=r"(r1), "=r"(r2), "=r"(r3) : "r"(addr));
}

__device__ __forceinline__ void mma_tf32(float* c, const uint32_t* a, const uint32_t* b) {
    asm volatile(
        "mma.sync.aligned.m16n8k8.row.col.f32.tf32.tf32.f32 "
        "{%0,%1,%2,%3}, {%4,%5,%6,%7}, {%8,%9}, {%0,%1,%2,%3};"
        : "+f"(c[0]), "+f"(c[1]), "+f"(c[2]), "+f"(c[3])
        : "r"(a[0]), "r"(a[1]), "r"(a[2]), "r"(a[3]), "r"(b[0]), "r"(b[1]));
}

__device__ __forceinline__ void cp_async16(uint32_t dst, const void* src) {
    asm volatile("cp.async.cg.shared.global [%0], [%1], 16;" :: "r"(dst), "l"(src));
}
__device__ __forceinline__ void cp_commit() {
    asm volatile("cp.async.commit_group;" ::: "memory");
}
template <int N>
__device__ __forceinline__ void cp_wait() {
    asm volatile("cp.async.wait_group %0;" :: "n"(N) : "memory");
}

// ---------------------------------------------------------------------------
// Kernel A: 4 blocks/sample popcount, 16 outstanding loads per thread
// (bandwidth-bound, not latency-bound), atomic reduce; last block finalizes.
// ---------------------------------------------------------------------------
__global__ __launch_bounds__(256) void len_mask_kernel(
    const int* __restrict__ mask,
    const int* __restrict__ branch_idx,
    float* __restrict__ out,
    int write_mask)
{
    const int b = blockIdx.x >> 2;
    const int q = blockIdx.x & 3;
    const int t = threadIdx.x;

    // quarter q of sample b: 16384 ints = 4096 uint4; thread t takes 16
    // consecutive-strided uint4s -> 16 independent loads in flight.
    const uint4* p = reinterpret_cast<const uint4*>(mask + (size_t)b * kT) + q * 4096;
    uint4 v[16];
#pragma unroll
    for (int j = 0; j < 16; j++) v[j] = p[t + j * 256];
    int sum = 0;
#pragma unroll
    for (int j = 0; j < 16; j++)
        sum += (int)((v[j].x & 1u) + (v[j].y & 1u) + (v[j].z & 1u) + (v[j].w & 1u));

#pragma unroll
    for (int o = 16; o > 0; o >>= 1) sum += __shfl_down_sync(0xffffffffu, sum, o);

    __shared__ int warp_sums[8];
    __shared__ int is_last;
    if ((t & 31) == 0) warp_sums[t >> 5] = sum;
    __syncthreads();
    if (t == 0) {
        int tot = 0;
#pragma unroll
        for (int i = 0; i < 8; i++) tot += warp_sums[i];
        atomicAdd(&g_cnt[b], tot);
        __threadfence();
        int old = atomicAdd(&g_done[b], 1);
        is_last = (old == 3);
    }
    __syncthreads();

    if (!is_last) return;

    __shared__ int nv_sh;
    if (t == 0) {
        __threadfence();
        int tot = atomicAdd(&g_cnt[b], 0);
        int bi = branch_idx[b];
        int w  = 128 << bi;
        int Sb = kT / w;
        int nv = tot / w;
        if (nv > Sb) nv = Sb;
        g_nvalid[b] = nv;
        nv_sh = nv;
        g_cnt[b]  = 0;
        g_done[b] = 0;
    }
    __syncthreads();

    if (write_mask) {
        int nv = nv_sh;
        float* mout = out + (size_t)kB * kSmax * kE + (size_t)b * kSmax;
        for (int s = t; s < kSmax; s += 256) mout[s] = (s < nv) ? 1.0f : 0.0f;
    }
}

// ---------------------------------------------------------------------------
// Kernel B: tf32 mma.sync GEMM (raw-fp32 fast path). CTA tile 64x128,
// 4 warps (32x64), ldmatrix + cp.async.cg double buffer, 4 CTAs/SM.
// Grid (4, 8, 128).  [UNCHANGED from R14 — proven 52.4us]
// ---------------------------------------------------------------------------
__global__ __launch_bounds__(NTHREADS, 4) void branch_gemm_mma(
    const float* __restrict__ signal,
    const int*   __restrict__ branch_idx,
    const float* __restrict__ W0, const float* __restrict__ b0,
    const float* __restrict__ W1, const float* __restrict__ b1,
    const float* __restrict__ W2, const float* __restrict__ b2,
    float* __restrict__ out)
{
    extern __shared__ float smemf[];
    const int tid  = threadIdx.x;
    const int b    = blockIdx.z;
    const int m0   = blockIdx.y * BM;
    const int n0   = blockIdx.x * BN;

    float* outb = out + (size_t)b * kSmax * kE;
    const int nv = g_nvalid[b];

    if (m0 >= nv) {
        float4 z = make_float4(0.f, 0.f, 0.f, 0.f);
#pragma unroll
        for (int i = 0; i < 16; i++) {
            int u   = tid + i * NTHREADS;
            int row = u >> 5;
            int c4  = (u & 31) << 2;
            *reinterpret_cast<float4*>(outb + (size_t)(m0 + row) * kE + n0 + c4) = z;
        }
        return;
    }

    const int bi   = branch_idx[b];
    const int logw = 7 + bi;
    const int nchunks = (1 << logw) / KC;     // 4, 8, 16
    const float* Wp = (bi == 0) ? W0 : (bi == 1) ? W1 : W2;
    const float* bp = (bi == 0) ? b0 : (bi == 1) ? b1 : b2;
    const float* Asrc = signal + (size_t)b * kT + ((size_t)m0 << logw);
    const float* Bsrc = Wp + ((size_t)n0 << logw);

    const uint32_t sbase = smem_u32(smemf);
    const int lane   = tid & 31;
    const int warp   = tid >> 5;
    const int warp_m = warp & 1;
    const int warp_n = warp >> 1;
    const int g      = lane >> 2;
    const int tg     = lane & 3;

    const int grp = lane >> 3;
    const int r8  = lane & 7;
    const uint32_t aRowBase = warp_m * 32 + (grp & 1) * 8 + r8;
    const uint32_t aColOff  = (grp >> 1) * 4;
    const uint32_t aAddr0 = sbase + (OFF_A + aRowBase * LDSF + aColOff) * 4;
    const uint32_t bRowBase = warp_n * 64 + (grp >> 1) * 8 + r8;
    const uint32_t bColOff  = (grp & 1) * 4;
    const uint32_t bAddr0 = sbase + (OFF_B + bRowBase * LDSF + bColOff) * 4;

    float acc[2][8][4];
#pragma unroll
    for (int mi = 0; mi < 2; mi++)
#pragma unroll
        for (int nj = 0; nj < 8; nj++)
#pragma unroll
            for (int q = 0; q < 4; q++) acc[mi][nj][q] = 0.f;

    const int lrow = tid >> 3;
    const int lc4  = (tid & 7) << 2;

    {
        uint32_t dA = sbase + (OFF_A + lrow * LDSF + lc4) * 4;
        uint32_t dB = sbase + (OFF_B + lrow * LDSF + lc4) * 4;
#pragma unroll
        for (int i = 0; i < 4; i++) {
            int row = lrow + i * 16;
            cp_async16(dA + i * 16 * LDSF * 4, Asrc + ((size_t)row << logw) + lc4);
        }
#pragma unroll
        for (int i = 0; i < 8; i++) {
            int row = lrow + i * 16;
            cp_async16(dB + i * 16 * LDSF * 4, Bsrc + ((size_t)row << logw) + lc4);
        }
        cp_commit();
    }

    for (int c = 0; c < nchunks; c++) {
        const uint32_t cbufB = (c & 1) * BUF_FLOATS * 4;
        const bool more = (c + 1 < nchunks);

        if (more) {
            const int kk = (c + 1) * KC;
            const uint32_t nb = ((c + 1) & 1) * BUF_FLOATS * 4;
            uint32_t dA = sbase + nb + (OFF_A + lrow * LDSF + lc4) * 4;
            uint32_t dB = sbase + nb + (OFF_B + lrow * LDSF + lc4) * 4;
#pragma unroll
            for (int i = 0; i < 4; i++) {
                int row = lrow + i * 16;
                cp_async16(dA + i * 16 * LDSF * 4, Asrc + ((size_t)row << logw) + kk + lc4);
            }
#pragma unroll
            for (int i = 0; i < 8; i++) {
                int row = lrow + i * 16;
                cp_async16(dB + i * 16 * LDSF * 4, Bsrc + ((size_t)row << logw) + kk + lc4);
            }
            cp_commit();
            cp_wait<1>();
        } else {
            cp_wait<0>();
        }
        __syncthreads();

#pragma unroll
        for (int s = 0; s < 4; s++) {
            const uint32_t ks = cbufB + s * 32;
            uint32_t af[2][4], bf[8][2];
#pragma unroll
            for (int mi = 0; mi < 2; mi++) {
                ldsm_x4(af[mi][0], af[mi][1], af[mi][2], af[mi][3],
                        aAddr0 + ks + mi * (16 * LDSF * 4));
            }
#pragma unroll
            for (int q = 0; q < 4; q++) {
                uint32_t r0, r1, r2, r3;
                ldsm_x4(r0, r1, r2, r3, bAddr0 + ks + q * (16 * LDSF * 4));
                bf[2 * q][0]     = r0;
                bf[2 * q][1]     = r1;
                bf[2 * q + 1][0] = r2;
                bf[2 * q + 1][1] = r3;
            }
#pragma unroll
            for (int mi = 0; mi < 2; mi++)
#pragma unroll
                for (int nj = 0; nj < 8; nj++)
                    mma_tf32(acc[mi][nj], af[mi], bf[nj]);
        }
        __syncthreads();
    }

    const int col0 = tg * 2;
    const int rbase = m0 + warp_m * 32 + g;
    const int ncol  = n0 + warp_n * 64;
#pragma unroll
    for (int mi = 0; mi < 2; mi++) {
        int r0 = rbase + mi * 16;
        int r1 = r0 + 8;
        bool v0 = r0 < nv, v1 = r1 < nv;
        float* o0p = outb + (size_t)r0 * kE + ncol + col0;
        float* o1p = outb + (size_t)r1 * kE + ncol + col0;
#pragma unroll
        for (int nj = 0; nj < 8; nj++) {
            float2 bias = *reinterpret_cast<const float2*>(bp + ncol + nj * 8 + col0);
            float2 o0 = v0 ? make_float2(acc[mi][nj][0] + bias.x, acc[mi][nj][1] + bias.y)
                           : make_float2(0.f, 0.f);
            float2 o1 = v1 ? make_float2(acc[mi][nj][2] + bias.x, acc[mi][nj][3] + bias.y)
                           : make_float2(0.f, 0.f);
            *reinterpret_cast<float2*>(o0p + nj * 8) = o0;
            *reinterpret_cast<float2*>(o1p + nj * 8) = o1;
        }
    }
}

// ---------------------------------------------------------------------------
extern "C" void kernel_launch(void* const* d_in, const int* in_sizes, int n_in,
                              void* d_out, int out_size)
{
    const float* signal = (const float*)d_in[0];
    const int*   mask   = (const int*)d_in[1];
    const int*   bidx   = (const int*)d_in[2];
    const float* W0 = (const float*)d_in[3];
    const float* b0 = (const float*)d_in[4];
    const float* W1 = (const float*)d_in[5];
    const float* b1 = (const float*)d_in[6];
    const float* W2 = (const float*)d_in[7];
    const float* b2 = (const float*)d_in[8];
    float* out = (float*)d_out;

    int write_mask = (out_size > kB * kSmax * kE) ? 1 : 0;

    len_mask_kernel<<<kB * 4, 256>>>(mask, bidx, out, write_mask);

    static bool attr_set = false;
    if (!attr_set) {
        cudaFuncSetAttribute(branch_gemm_mma,
                             cudaFuncAttributeMaxDynamicSharedMemorySize, SMEM_BYTES);
        attr_set = true;
    }
    dim3 grid(kE / BN, kSmax / BM, kB);
    branch_gemm_mma<<<grid, NTHREADS, SMEM_BYTES>>>(signal, bidx, W0, b0, W1, b1, W2, b2, out);
}